// round 16
// baseline (speedup 1.0000x reference)
#include <cuda_runtime.h>
#include <cuda_bf16.h>
#include <stdint.h>
#include <math.h>

#define T_TOK 8192      // B*S
#define DIM   1024
#define NEXP  8
#define LN_EPS 1e-5f

#define BM 128
#define BN 128
#define KC 32
#define NCHUNK (DIM / KC)   // 32
#define NSTAGE 3

// ---------------- static device scratch (allocation-guard safe) --------------
__device__ int      g_count[NEXP];
__device__ int      g_tok[NEXP * T_TOK];
__device__ int      g_te[2 * T_TOK];
__device__ int      g_ts[2 * T_TOK];
__device__ float    g_tw[2 * T_TOK];
__device__ uint32_t g_xt[T_TOK * DIM];              // x rounded to tf32
__device__ uint32_t g_wt[NEXP * DIM * DIM];         // W transposed [e][n][k], tf32
__device__ float    g_y[2 * T_TOK * DIM];           // compacted expert outputs

// ---------------- helpers ----------------------------------------------------
__device__ __forceinline__ uint32_t smem_u32(const void* p) {
    uint32_t a;
    asm("{ .reg .u64 t; cvta.to.shared.u64 t, %1; cvt.u32.u64 %0, t; }"
        : "=r"(a) : "l"(p));
    return a;
}

__device__ __forceinline__ uint32_t f2tf32(float v) {
    uint32_t u;
    asm("cvt.rna.tf32.f32 %0, %1;" : "=r"(u) : "f"(v));
    return u;
}

// SW128 swizzle on byte offsets within 128B-row tiles
#define SWZ(o) ((uint32_t)(o) ^ ((((uint32_t)(o)) >> 3) & 0x70u))

#define CP_ASYNC16(dst_u32, src_ptr) \
    asm volatile("{ .reg .u64 g; cvta.to.global.u64 g, %1; " \
                 "cp.async.cg.shared.global [%0], [g], 16; }" \
                 :: "r"(dst_u32), "l"(src_ptr) : "memory")

#define CP_COMMIT() asm volatile("cp.async.commit_group;" ::: "memory")
#define CP_WAIT1()  asm volatile("cp.async.wait_group 1;" ::: "memory")

#define LDSM4(r, addr) \
    asm volatile("ldmatrix.sync.aligned.m8n8.x4.shared.b16 {%0,%1,%2,%3}, [%4];" \
                 : "=r"((r)[0]), "=r"((r)[1]), "=r"((r)[2]), "=r"((r)[3]) \
                 : "r"(addr))

#define MMA_TF32(d, a, b0, b1) \
    asm volatile("mma.sync.aligned.m16n8k8.row.col.f32.tf32.tf32.f32 " \
                 "{%0,%1,%2,%3}, {%4,%5,%6,%7}, {%8,%9}, {%0,%1,%2,%3};" \
                 : "+f"((d)[0]), "+f"((d)[1]), "+f"((d)[2]), "+f"((d)[3]) \
                 : "r"((a)[0]), "r"((a)[1]), "r"((a)[2]), "r"((a)[3]), \
                   "r"(b0), "r"(b1))

// ---------------- small kernels ---------------------------------------------
__global__ void zero_counts_kernel() {
    if (threadIdx.x < NEXP) g_count[threadIdx.x] = 0;
}

// transpose W[e][k][n] -> g_wt[e][n][k], tf32, 64x64 tiles, float4 both ways
__global__ void __launch_bounds__(256) convert_w_kernel(const float* __restrict__ W) {
    __shared__ float tile[64][65];
    int e  = blockIdx.z;
    int k0 = blockIdx.x * 64;
    int n0 = blockIdx.y * 64;
    int t  = threadIdx.x;
    int c4 = t & 15;          // float4 column group
    int r  = t >> 4;          // 0..15

    const float* Wb = W + ((size_t)e * DIM + k0) * DIM + n0;
    #pragma unroll
    for (int i = 0; i < 4; i++) {
        int row = r + 16 * i;
        float4 v = *(const float4*)(Wb + (size_t)row * DIM + c4 * 4);
        tile[row][c4 * 4 + 0] = v.x;
        tile[row][c4 * 4 + 1] = v.y;
        tile[row][c4 * 4 + 2] = v.z;
        tile[row][c4 * 4 + 3] = v.w;
    }
    __syncthreads();
    size_t wb = ((size_t)e * DIM + n0) * DIM + k0;
    #pragma unroll
    for (int i = 0; i < 4; i++) {
        int n = r + 16 * i;
        uint4 o;
        o.x = f2tf32(tile[c4 * 4 + 0][n]);
        o.y = f2tf32(tile[c4 * 4 + 1][n]);
        o.z = f2tf32(tile[c4 * 4 + 2][n]);
        o.w = f2tf32(tile[c4 * 4 + 3][n]);
        *(uint4*)(g_wt + wb + (size_t)n * DIM + c4 * 4) = o;
    }
}

// ---------------- routing (one warp per token) + fused x->tf32 ---------------
__global__ void __launch_bounds__(256) routing_kernel(
    const float* __restrict__ x,
    const float* __restrict__ noise,
    const float* __restrict__ Wr,
    const float* __restrict__ br,
    const float* __restrict__ gamma,
    const float* __restrict__ beta)
{
    int warp = (blockIdx.x * blockDim.x + threadIdx.x) >> 5;
    int lane = threadIdx.x & 31;
    if (warp >= T_TOK) return;

    const float* xr = x + (size_t)warp * DIM;
    float acc[NEXP];
    #pragma unroll
    for (int e = 0; e < NEXP; e++) acc[e] = 0.f;

    for (int d = lane; d < DIM; d += 32) {
        float xv = xr[d];
        g_xt[(size_t)warp * DIM + d] = f2tf32(xv);     // fused conversion
        const float4* w4 = (const float4*)(Wr + (size_t)d * NEXP);
        float4 wa = w4[0];
        float4 wb = w4[1];
        acc[0] = fmaf(xv, wa.x, acc[0]);
        acc[1] = fmaf(xv, wa.y, acc[1]);
        acc[2] = fmaf(xv, wa.z, acc[2]);
        acc[3] = fmaf(xv, wa.w, acc[3]);
        acc[4] = fmaf(xv, wb.x, acc[4]);
        acc[5] = fmaf(xv, wb.y, acc[5]);
        acc[6] = fmaf(xv, wb.z, acc[6]);
        acc[7] = fmaf(xv, wb.w, acc[7]);
    }
    #pragma unroll
    for (int e = 0; e < NEXP; e++) {
        #pragma unroll
        for (int off = 16; off > 0; off >>= 1)
            acc[e] += __shfl_xor_sync(0xffffffffu, acc[e], off);
    }

    if (lane == 0) {
        float l[NEXP];
        float mu = 0.f;
        #pragma unroll
        for (int e = 0; e < NEXP; e++) { l[e] = acc[e] + br[e]; mu += l[e]; }
        mu *= 0.125f;
        float var = 0.f;
        #pragma unroll
        for (int e = 0; e < NEXP; e++) { float d = l[e] - mu; var += d * d; }
        var *= 0.125f;
        float inv = rsqrtf(var + LN_EPS);
        float mx = -1e30f;
        #pragma unroll
        for (int e = 0; e < NEXP; e++) {
            l[e] = (l[e] - mu) * inv * gamma[e] + beta[e];
            mx = fmaxf(mx, l[e]);
        }
        float den = 0.f;
        #pragma unroll
        for (int e = 0; e < NEXP; e++) { l[e] = expf(l[e] - mx); den += l[e]; }
        float rden = 1.f / den;
        const float* nrow = noise + (size_t)warp * NEXP;
        #pragma unroll
        for (int e = 0; e < NEXP; e++) l[e] = l[e] * rden + nrow[e];

        int i0 = 0; float v0 = l[0];
        #pragma unroll
        for (int e = 1; e < NEXP; e++) if (l[e] > v0) { v0 = l[e]; i0 = e; }
        int i1 = -1; float v1 = -1e30f;
        #pragma unroll
        for (int e = 0; e < NEXP; e++) if (e != i0 && l[e] > v1) { v1 = l[e]; i1 = e; }

        float e1 = expf(v1 - v0);
        float w0 = 1.f / (1.f + e1);
        float w1 = e1 * w0;

        int s0 = atomicAdd(&g_count[i0], 1);
        g_tok[i0 * T_TOK + s0] = warp;
        g_te[2 * warp] = i0; g_ts[2 * warp] = s0; g_tw[2 * warp] = w0;
        int s1 = atomicAdd(&g_count[i1], 1);
        g_tok[i1 * T_TOK + s1] = warp;
        g_te[2 * warp + 1] = i1; g_ts[2 * warp + 1] = s1; g_tw[2 * warp + 1] = w1;
    }
}

// ---------------- grouped GEMM: tf32, 3-stage cp.async, ONE sync per chunk ---
// stage (KC=32 tf32 -> 128B rows): A [128][128B] 16KB | B [128][128B] 16KB
#define SM_A      0
#define SM_B      16384
#define SM_STAGE  32768
#define SM_TILES  1024
#define SMEM_TOTAL (SM_TILES + NSTAGE * SM_STAGE)

__global__ void __launch_bounds__(256, 2) moe_gemm_kernel() {
    extern __shared__ char smem[];
    const int tilesPerExp = T_TOK / BM;         // 64
    int e    = blockIdx.x / tilesPerExp;
    int mt   = blockIdx.x % tilesPerExp;
    int cnt  = g_count[e];
    int row0 = mt * BM;
    if (row0 >= cnt) return;
    int n0   = blockIdx.y * BN;
    int offe = 0;
    for (int q = 0; q < NEXP; q++) offe += (q < e) ? g_count[q] : 0;

    uint32_t sb = smem_u32(smem);
    int tid  = threadIdx.x;
    int wid  = tid >> 5;
    int lane = tid & 31;

    int* s_tok = (int*)smem;
    if (tid < BM) {
        int r = row0 + tid;
        s_tok[tid] = (r < cnt) ? g_tok[e * T_TOK + r] : 0;   // pad rows read token 0
    }
    __syncthreads();

    int lrow = tid >> 3;          // 0..31
    int sg   = tid & 7;           // 16B segment within 128B row

    auto issue_stage = [&](int s, int k0) {
        uint32_t stage = sb + SM_TILES + s * SM_STAGE;
        #pragma unroll
        for (int i = 0; i < 4; i++) {               // A: 128 rows x 8 segs
            int row = lrow + 32 * i;
            int t = s_tok[row];
            uint32_t d = SWZ(row * 128 + sg * 16);
            CP_ASYNC16(stage + SM_A + d, g_xt + (size_t)t * DIM + k0 + sg * 4);
        }
        #pragma unroll
        for (int i = 0; i < 4; i++) {               // B: 128 rows x 8 segs
            int row = lrow + 32 * i;
            uint32_t d = SWZ(row * 128 + sg * 16);
            size_t go = ((size_t)e * DIM + n0 + row) * DIM + k0 + sg * 4;
            CP_ASYNC16(stage + SM_B + d, g_wt + go);
        }
        CP_COMMIT();
    };

    // warp tile 32x64: warps 4(m) x 2(n)
    int wm = (wid >> 1) * 32;
    int wn = (wid & 1) * 64;

    float acc[2][8][4];
    #pragma unroll
    for (int i = 0; i < 2; i++)
        #pragma unroll
        for (int j = 0; j < 8; j++)
            #pragma unroll
            for (int q = 0; q < 4; q++) acc[i][j][q] = 0.f;

    // ldmatrix lane mapping: lane L -> matrix j=L>>3, row r=L&7
    int jm = lane >> 3;
    int jr = lane & 7;
    uint32_t aRow = (uint32_t)(wm + ((jm & 1) << 3) + jr);
    uint32_t aK   = (uint32_t)((jm >> 1) << 4);
    uint32_t bRow = (uint32_t)(wn + ((jm >> 1) << 3) + jr);
    uint32_t bK   = (uint32_t)((jm & 1) << 4);

    issue_stage(0, 0);
    issue_stage(1, KC);

    // ONE barrier per chunk: wait(stage c) -> sync -> issue(stage c+2) -> compute.
    for (int c = 0; c < NCHUNK; c++) {
        int s = c % NSTAGE;
        CP_WAIT1();
        __syncthreads();
        if (c + 2 < NCHUNK) {
            int c2 = c + 2;
            issue_stage(c2 % NSTAGE, c2 * KC);
        } else {
            CP_COMMIT();            // empty group keeps count uniform
        }

        uint32_t stage = sb + SM_TILES + s * SM_STAGE;
        uint32_t sA = stage + SM_A, sB = stage + SM_B;

        #pragma unroll
        for (int kb = 0; kb < 4; kb++) {
            uint32_t a[2][4];
            #pragma unroll
            for (int mf = 0; mf < 2; mf++) {
                uint32_t off = SWZ((aRow + mf * 16) * 128 + kb * 32 + aK);
                LDSM4(a[mf], sA + off);
            }
            #pragma unroll
            for (int ng = 0; ng < 4; ng++) {
                uint32_t b[4];
                uint32_t off = SWZ((bRow + ng * 16) * 128 + kb * 32 + bK);
                LDSM4(b, sB + off);
                #pragma unroll
                for (int mf = 0; mf < 2; mf++) {
                    MMA_TF32(acc[mf][2 * ng],     a[mf], b[0], b[1]);
                    MMA_TF32(acc[mf][2 * ng + 1], a[mf], b[2], b[3]);
                }
            }
        }
    }

    // ---- epilogue: registers -> g_y (compacted rows) ----
    int g   = lane >> 2;
    int tig = lane & 3;
    #pragma unroll
    for (int mf = 0; mf < 2; mf++) {
        int r0 = row0 + wm + mf * 16 + g;
        #pragma unroll
        for (int nf = 0; nf < 8; nf++) {
            int col = n0 + wn + nf * 8 + tig * 2;
            if (r0 < cnt) {
                float2 v = make_float2(acc[mf][nf][0], acc[mf][nf][1]);
                *(float2*)(g_y + (size_t)(offe + r0) * DIM + col) = v;
            }
            if (r0 + 8 < cnt) {
                float2 v = make_float2(acc[mf][nf][2], acc[mf][nf][3]);
                *(float2*)(g_y + (size_t)(offe + r0 + 8) * DIM + col) = v;
            }
        }
    }
}

// ---------------- combine: out = w0*(y0+b0) + w1*(y1+b1) ---------------------
__global__ void __launch_bounds__(256) combine_kernel(
    const float* __restrict__ b_exp, float* __restrict__ out)
{
    int t = blockIdx.x;
    int e0 = g_te[2 * t],     e1 = g_te[2 * t + 1];
    float w0 = g_tw[2 * t],   w1 = g_tw[2 * t + 1];
    int off0 = 0, off1 = 0;
    #pragma unroll
    for (int q = 0; q < NEXP; q++) {
        int cq = g_count[q];
        off0 += (q < e0) ? cq : 0;
        off1 += (q < e1) ? cq : 0;
    }
    int p0 = off0 + g_ts[2 * t];
    int p1 = off1 + g_ts[2 * t + 1];
    int c = threadIdx.x * 4;

    float4 y0 = *(const float4*)(g_y + (size_t)p0 * DIM + c);
    float4 y1 = *(const float4*)(g_y + (size_t)p1 * DIM + c);
    float4 b0 = *(const float4*)(b_exp + (size_t)e0 * DIM + c);
    float4 b1 = *(const float4*)(b_exp + (size_t)e1 * DIM + c);
    float4 o;
    o.x = w0 * (y0.x + b0.x) + w1 * (y1.x + b1.x);
    o.y = w0 * (y0.y + b0.y) + w1 * (y1.y + b1.y);
    o.z = w0 * (y0.z + b0.z) + w1 * (y1.z + b1.z);
    o.w = w0 * (y0.w + b0.w) + w1 * (y1.w + b1.w);
    *(float4*)(out + (size_t)t * DIM + c) = o;
}

// ---------------- launch -----------------------------------------------------
extern "C" void kernel_launch(void* const* d_in, const int* in_sizes, int n_in,
                              void* d_out, int out_size)
{
    const float* x     = (const float*)d_in[0];
    const float* noise = (const float*)d_in[1];
    const float* Wr    = (const float*)d_in[2];
    const float* br    = (const float*)d_in[3];
    const float* gam   = (const float*)d_in[4];
    const float* bet   = (const float*)d_in[5];
    const float* W_exp = (const float*)d_in[6];
    const float* b_exp = (const float*)d_in[7];
    float* out = (float*)d_out;

    cudaFuncSetAttribute(moe_gemm_kernel,
                         cudaFuncAttributeMaxDynamicSharedMemorySize, SMEM_TOTAL);

    zero_counts_kernel<<<1, 32>>>();
    routing_kernel<<<T_TOK * 32 / 256, 256>>>(x, noise, Wr, br, gam, bet);
    convert_w_kernel<<<dim3(DIM / 64, DIM / 64, NEXP), 256>>>(W_exp);

    dim3 grid(NEXP * (T_TOK / BM), DIM / BN);
    moe_gemm_kernel<<<grid, 256, SMEM_TOTAL>>>();

    combine_kernel<<<T_TOK, 256>>>(b_exp, out);
}

// round 17
// speedup vs baseline: 1.0147x; 1.0147x over previous
#include <cuda_runtime.h>
#include <cuda_bf16.h>
#include <cuda_fp16.h>
#include <stdint.h>
#include <math.h>

#define T_TOK 8192      // B*S
#define DIM   1024
#define NEXP  8
#define LN_EPS 1e-5f

#define BM 128
#define BN 128
#define KC 32
#define NCHUNK (DIM / KC)   // 32
#define NSTAGE 3

// ---------------- static device scratch (allocation-guard safe) --------------
__device__ int      g_count[NEXP];
__device__ int      g_tok[NEXP * T_TOK];
__device__ int      g_te[2 * T_TOK];
__device__ int      g_ts[2 * T_TOK];
__device__ float    g_tw[2 * T_TOK];
__device__ uint32_t g_xt[T_TOK * DIM];              // x rounded to tf32
__device__ uint32_t g_wt[NEXP * DIM * DIM];         // W transposed [e][n][k], tf32
__device__ __half   g_y[2 * T_TOK * DIM];           // compacted expert outputs (fp16)

// ---------------- helpers ----------------------------------------------------
__device__ __forceinline__ uint32_t smem_u32(const void* p) {
    uint32_t a;
    asm("{ .reg .u64 t; cvta.to.shared.u64 t, %1; cvt.u32.u64 %0, t; }"
        : "=r"(a) : "l"(p));
    return a;
}

__device__ __forceinline__ uint32_t f2tf32(float v) {
    uint32_t u;
    asm("cvt.rna.tf32.f32 %0, %1;" : "=r"(u) : "f"(v));
    return u;
}

// SW128 swizzle on byte offsets within 128B-row tiles
#define SWZ(o) ((uint32_t)(o) ^ ((((uint32_t)(o)) >> 3) & 0x70u))

#define CP_ASYNC16(dst_u32, src_ptr) \
    asm volatile("{ .reg .u64 g; cvta.to.global.u64 g, %1; " \
                 "cp.async.cg.shared.global [%0], [g], 16; }" \
                 :: "r"(dst_u32), "l"(src_ptr) : "memory")

#define CP_COMMIT() asm volatile("cp.async.commit_group;" ::: "memory")
#define CP_WAIT1()  asm volatile("cp.async.wait_group 1;" ::: "memory")

#define LDSM4(r, addr) \
    asm volatile("ldmatrix.sync.aligned.m8n8.x4.shared.b16 {%0,%1,%2,%3}, [%4];" \
                 : "=r"((r)[0]), "=r"((r)[1]), "=r"((r)[2]), "=r"((r)[3]) \
                 : "r"(addr))

#define MMA_TF32(d, a, b0, b1) \
    asm volatile("mma.sync.aligned.m16n8k8.row.col.f32.tf32.tf32.f32 " \
                 "{%0,%1,%2,%3}, {%4,%5,%6,%7}, {%8,%9}, {%0,%1,%2,%3};" \
                 : "+f"((d)[0]), "+f"((d)[1]), "+f"((d)[2]), "+f"((d)[3]) \
                 : "r"((a)[0]), "r"((a)[1]), "r"((a)[2]), "r"((a)[3]), \
                   "r"(b0), "r"(b1))

// ---------------- small kernels ---------------------------------------------
__global__ void zero_counts_kernel() {
    if (threadIdx.x < NEXP) g_count[threadIdx.x] = 0;
}

// transpose W[e][k][n] -> g_wt[e][n][k], tf32, 64x64 tiles, float4 both ways
__global__ void __launch_bounds__(256) convert_w_kernel(const float* __restrict__ W) {
    __shared__ float tile[64][65];
    int e  = blockIdx.z;
    int k0 = blockIdx.x * 64;
    int n0 = blockIdx.y * 64;
    int t  = threadIdx.x;
    int c4 = t & 15;          // float4 column group
    int r  = t >> 4;          // 0..15

    const float* Wb = W + ((size_t)e * DIM + k0) * DIM + n0;
    #pragma unroll
    for (int i = 0; i < 4; i++) {
        int row = r + 16 * i;
        float4 v = *(const float4*)(Wb + (size_t)row * DIM + c4 * 4);
        tile[row][c4 * 4 + 0] = v.x;
        tile[row][c4 * 4 + 1] = v.y;
        tile[row][c4 * 4 + 2] = v.z;
        tile[row][c4 * 4 + 3] = v.w;
    }
    __syncthreads();
    size_t wb = ((size_t)e * DIM + n0) * DIM + k0;
    #pragma unroll
    for (int i = 0; i < 4; i++) {
        int n = r + 16 * i;
        uint4 o;
        o.x = f2tf32(tile[c4 * 4 + 0][n]);
        o.y = f2tf32(tile[c4 * 4 + 1][n]);
        o.z = f2tf32(tile[c4 * 4 + 2][n]);
        o.w = f2tf32(tile[c4 * 4 + 3][n]);
        *(uint4*)(g_wt + wb + (size_t)n * DIM + c4 * 4) = o;
    }
}

// ---------------- routing (one warp per token) + fused x->tf32 ---------------
__global__ void __launch_bounds__(256) routing_kernel(
    const float* __restrict__ x,
    const float* __restrict__ noise,
    const float* __restrict__ Wr,
    const float* __restrict__ br,
    const float* __restrict__ gamma,
    const float* __restrict__ beta)
{
    int warp = (blockIdx.x * blockDim.x + threadIdx.x) >> 5;
    int lane = threadIdx.x & 31;
    if (warp >= T_TOK) return;

    const float* xr = x + (size_t)warp * DIM;
    float acc[NEXP];
    #pragma unroll
    for (int e = 0; e < NEXP; e++) acc[e] = 0.f;

    for (int d = lane; d < DIM; d += 32) {
        float xv = xr[d];
        g_xt[(size_t)warp * DIM + d] = f2tf32(xv);     // fused conversion
        const float4* w4 = (const float4*)(Wr + (size_t)d * NEXP);
        float4 wa = w4[0];
        float4 wb = w4[1];
        acc[0] = fmaf(xv, wa.x, acc[0]);
        acc[1] = fmaf(xv, wa.y, acc[1]);
        acc[2] = fmaf(xv, wa.z, acc[2]);
        acc[3] = fmaf(xv, wa.w, acc[3]);
        acc[4] = fmaf(xv, wb.x, acc[4]);
        acc[5] = fmaf(xv, wb.y, acc[5]);
        acc[6] = fmaf(xv, wb.z, acc[6]);
        acc[7] = fmaf(xv, wb.w, acc[7]);
    }
    #pragma unroll
    for (int e = 0; e < NEXP; e++) {
        #pragma unroll
        for (int off = 16; off > 0; off >>= 1)
            acc[e] += __shfl_xor_sync(0xffffffffu, acc[e], off);
    }

    if (lane == 0) {
        float l[NEXP];
        float mu = 0.f;
        #pragma unroll
        for (int e = 0; e < NEXP; e++) { l[e] = acc[e] + br[e]; mu += l[e]; }
        mu *= 0.125f;
        float var = 0.f;
        #pragma unroll
        for (int e = 0; e < NEXP; e++) { float d = l[e] - mu; var += d * d; }
        var *= 0.125f;
        float inv = rsqrtf(var + LN_EPS);
        float mx = -1e30f;
        #pragma unroll
        for (int e = 0; e < NEXP; e++) {
            l[e] = (l[e] - mu) * inv * gamma[e] + beta[e];
            mx = fmaxf(mx, l[e]);
        }
        float den = 0.f;
        #pragma unroll
        for (int e = 0; e < NEXP; e++) { l[e] = expf(l[e] - mx); den += l[e]; }
        float rden = 1.f / den;
        const float* nrow = noise + (size_t)warp * NEXP;
        #pragma unroll
        for (int e = 0; e < NEXP; e++) l[e] = l[e] * rden + nrow[e];

        int i0 = 0; float v0 = l[0];
        #pragma unroll
        for (int e = 1; e < NEXP; e++) if (l[e] > v0) { v0 = l[e]; i0 = e; }
        int i1 = -1; float v1 = -1e30f;
        #pragma unroll
        for (int e = 0; e < NEXP; e++) if (e != i0 && l[e] > v1) { v1 = l[e]; i1 = e; }

        float e1 = expf(v1 - v0);
        float w0 = 1.f / (1.f + e1);
        float w1 = e1 * w0;

        int s0 = atomicAdd(&g_count[i0], 1);
        g_tok[i0 * T_TOK + s0] = warp;
        g_te[2 * warp] = i0; g_ts[2 * warp] = s0; g_tw[2 * warp] = w0;
        int s1 = atomicAdd(&g_count[i1], 1);
        g_tok[i1 * T_TOK + s1] = warp;
        g_te[2 * warp + 1] = i1; g_ts[2 * warp + 1] = s1; g_tw[2 * warp + 1] = w1;
    }
}

// ---------------- grouped GEMM: tf32, 3-stage cp.async, ONE sync per chunk ---
// stage (KC=32 tf32 -> 128B rows): A [128][128B] 16KB | B [128][128B] 16KB
#define SM_A      0
#define SM_B      16384
#define SM_STAGE  32768
#define SM_TILES  1024
#define SMEM_TOTAL (SM_TILES + NSTAGE * SM_STAGE)

__global__ void __launch_bounds__(256, 2) moe_gemm_kernel() {
    extern __shared__ char smem[];
    const int tilesPerExp = T_TOK / BM;         // 64
    int e    = blockIdx.x / tilesPerExp;
    int mt   = blockIdx.x % tilesPerExp;
    int cnt  = g_count[e];
    int row0 = mt * BM;
    if (row0 >= cnt) return;
    int n0   = blockIdx.y * BN;
    int offe = 0;
    for (int q = 0; q < NEXP; q++) offe += (q < e) ? g_count[q] : 0;

    uint32_t sb = smem_u32(smem);
    int tid  = threadIdx.x;
    int wid  = tid >> 5;
    int lane = tid & 31;

    int* s_tok = (int*)smem;
    if (tid < BM) {
        int r = row0 + tid;
        s_tok[tid] = (r < cnt) ? g_tok[e * T_TOK + r] : 0;   // pad rows read token 0
    }
    __syncthreads();

    int lrow = tid >> 3;          // 0..31
    int sg   = tid & 7;           // 16B segment within 128B row

    auto issue_stage = [&](int s, int k0) {
        uint32_t stage = sb + SM_TILES + s * SM_STAGE;
        #pragma unroll
        for (int i = 0; i < 4; i++) {               // A: 128 rows x 8 segs
            int row = lrow + 32 * i;
            int t = s_tok[row];
            uint32_t d = SWZ(row * 128 + sg * 16);
            CP_ASYNC16(stage + SM_A + d, g_xt + (size_t)t * DIM + k0 + sg * 4);
        }
        #pragma unroll
        for (int i = 0; i < 4; i++) {               // B: 128 rows x 8 segs
            int row = lrow + 32 * i;
            uint32_t d = SWZ(row * 128 + sg * 16);
            size_t go = ((size_t)e * DIM + n0 + row) * DIM + k0 + sg * 4;
            CP_ASYNC16(stage + SM_B + d, g_wt + go);
        }
        CP_COMMIT();
    };

    // warp tile 32x64: warps 4(m) x 2(n)
    int wm = (wid >> 1) * 32;
    int wn = (wid & 1) * 64;

    float acc[2][8][4];
    #pragma unroll
    for (int i = 0; i < 2; i++)
        #pragma unroll
        for (int j = 0; j < 8; j++)
            #pragma unroll
            for (int q = 0; q < 4; q++) acc[i][j][q] = 0.f;

    // ldmatrix lane mapping: lane L -> matrix j=L>>3, row r=L&7
    int jm = lane >> 3;
    int jr = lane & 7;
    uint32_t aRow = (uint32_t)(wm + ((jm & 1) << 3) + jr);
    uint32_t aK   = (uint32_t)((jm >> 1) << 4);
    uint32_t bRow = (uint32_t)(wn + ((jm >> 1) << 3) + jr);
    uint32_t bK   = (uint32_t)((jm & 1) << 4);

    issue_stage(0, 0);
    issue_stage(1, KC);

    // ONE barrier per chunk: wait(stage c) -> sync -> issue(stage c+2) -> compute.
    for (int c = 0; c < NCHUNK; c++) {
        int s = c % NSTAGE;
        CP_WAIT1();
        __syncthreads();
        if (c + 2 < NCHUNK) {
            int c2 = c + 2;
            issue_stage(c2 % NSTAGE, c2 * KC);
        } else {
            CP_COMMIT();            // empty group keeps count uniform
        }

        uint32_t stage = sb + SM_TILES + s * SM_STAGE;
        uint32_t sA = stage + SM_A, sB = stage + SM_B;

        #pragma unroll
        for (int kb = 0; kb < 4; kb++) {
            uint32_t a[2][4];
            #pragma unroll
            for (int mf = 0; mf < 2; mf++) {
                uint32_t off = SWZ((aRow + mf * 16) * 128 + kb * 32 + aK);
                LDSM4(a[mf], sA + off);
            }
            #pragma unroll
            for (int ng = 0; ng < 4; ng++) {
                uint32_t b[4];
                uint32_t off = SWZ((bRow + ng * 16) * 128 + kb * 32 + bK);
                LDSM4(b, sB + off);
                #pragma unroll
                for (int mf = 0; mf < 2; mf++) {
                    MMA_TF32(acc[mf][2 * ng],     a[mf], b[0], b[1]);
                    MMA_TF32(acc[mf][2 * ng + 1], a[mf], b[2], b[3]);
                }
            }
        }
    }

    // ---- epilogue: registers -> g_y (fp16, compacted rows) ----
    int g   = lane >> 2;
    int tig = lane & 3;
    #pragma unroll
    for (int mf = 0; mf < 2; mf++) {
        int r0 = row0 + wm + mf * 16 + g;
        #pragma unroll
        for (int nf = 0; nf < 8; nf++) {
            int col = n0 + wn + nf * 8 + tig * 2;
            if (r0 < cnt) {
                __half2 v = __floats2half2_rn(acc[mf][nf][0], acc[mf][nf][1]);
                *(__half2*)(g_y + (size_t)(offe + r0) * DIM + col) = v;
            }
            if (r0 + 8 < cnt) {
                __half2 v = __floats2half2_rn(acc[mf][nf][2], acc[mf][nf][3]);
                *(__half2*)(g_y + (size_t)(offe + r0 + 8) * DIM + col) = v;
            }
        }
    }
}

// ---------------- combine: out = w0*(y0+b0) + w1*(y1+b1)  (y in fp16) --------
__global__ void __launch_bounds__(256) combine_kernel(
    const float* __restrict__ b_exp, float* __restrict__ out)
{
    int t = blockIdx.x;
    int e0 = g_te[2 * t],     e1 = g_te[2 * t + 1];
    float w0 = g_tw[2 * t],   w1 = g_tw[2 * t + 1];
    int off0 = 0, off1 = 0;
    #pragma unroll
    for (int q = 0; q < NEXP; q++) {
        int cq = g_count[q];
        off0 += (q < e0) ? cq : 0;
        off1 += (q < e1) ? cq : 0;
    }
    int p0 = off0 + g_ts[2 * t];
    int p1 = off1 + g_ts[2 * t + 1];
    int c = threadIdx.x * 4;

    // 4 halves = 8 bytes per token row (aligned: c % 4 == 0 -> 8B aligned)
    uint2 yr0 = *(const uint2*)(g_y + (size_t)p0 * DIM + c);
    uint2 yr1 = *(const uint2*)(g_y + (size_t)p1 * DIM + c);
    float2 y0a = __half22float2(*(__half2*)&yr0.x);
    float2 y0b = __half22float2(*(__half2*)&yr0.y);
    float2 y1a = __half22float2(*(__half2*)&yr1.x);
    float2 y1b = __half22float2(*(__half2*)&yr1.y);

    float4 b0 = *(const float4*)(b_exp + (size_t)e0 * DIM + c);
    float4 b1 = *(const float4*)(b_exp + (size_t)e1 * DIM + c);
    float4 o;
    o.x = w0 * (y0a.x + b0.x) + w1 * (y1a.x + b1.x);
    o.y = w0 * (y0a.y + b0.y) + w1 * (y1a.y + b1.y);
    o.z = w0 * (y0b.x + b0.z) + w1 * (y1b.x + b1.z);
    o.w = w0 * (y0b.y + b0.w) + w1 * (y1b.y + b1.w);
    *(float4*)(out + (size_t)t * DIM + c) = o;
}

// ---------------- launch -----------------------------------------------------
extern "C" void kernel_launch(void* const* d_in, const int* in_sizes, int n_in,
                              void* d_out, int out_size)
{
    const float* x     = (const float*)d_in[0];
    const float* noise = (const float*)d_in[1];
    const float* Wr    = (const float*)d_in[2];
    const float* br    = (const float*)d_in[3];
    const float* gam   = (const float*)d_in[4];
    const float* bet   = (const float*)d_in[5];
    const float* W_exp = (const float*)d_in[6];
    const float* b_exp = (const float*)d_in[7];
    float* out = (float*)d_out;

    cudaFuncSetAttribute(moe_gemm_kernel,
                         cudaFuncAttributeMaxDynamicSharedMemorySize, SMEM_TOTAL);

    zero_counts_kernel<<<1, 32>>>();
    routing_kernel<<<T_TOK * 32 / 256, 256>>>(x, noise, Wr, br, gam, bet);
    convert_w_kernel<<<dim3(DIM / 64, DIM / 64, NEXP), 256>>>(W_exp);

    dim3 grid(NEXP * (T_TOK / BM), DIM / BN);
    moe_gemm_kernel<<<grid, 256, SMEM_TOTAL>>>();

    combine_kernel<<<T_TOK, 256>>>(b_exp, out);
}